// round 15
// baseline (speedup 1.0000x reference)
#include <cuda_runtime.h>

#define NW      10
#define DIM     1024
#define THREADS 128

typedef unsigned long long ull;

// ---------- packed f32x2 helpers ----------
__device__ __forceinline__ ull pk(float lo, float hi) {
    ull r;
    asm("mov.b64 %0, {%1, %2};" : "=l"(r)
        : "r"(__float_as_uint(lo)), "r"(__float_as_uint(hi)));
    return r;
}
__device__ __forceinline__ void upk(ull v, float& lo, float& hi) {
    unsigned a, b;
    asm("mov.b64 {%0, %1}, %2;" : "=r"(a), "=r"(b) : "l"(v));
    lo = __uint_as_float(a); hi = __uint_as_float(b);
}
__device__ __forceinline__ ull swp(ull v) {
    float lo, hi; upk(v, lo, hi); return pk(hi, lo);
}
__device__ __forceinline__ ull fma2(ull a, ull b, ull c) {
    ull d;
    asm("fma.rn.f32x2 %0, %1, %2, %3;" : "=l"(d) : "l"(a), "l"(b), "l"(c));
    return d;
}
__device__ __forceinline__ ull mul2(ull a, ull b) {
    ull d;
    asm("mul.rn.f32x2 %0, %1, %2;" : "=l"(d) : "l"(a), "l"(b));
    return d;
}

// smem coefficient bank layout (ull indices):
// [ 0..39]  lane complex gates q5..q9: (j-5)*8 + {a2 ai2 b2 bi2 c2 ci2 d2 di2}
//           (full gates, cos factors NOT deferred for these)
// [40..54]  t-gates q0..q4 layer1:  40 + j*3 + {tx2=(tx,-tx), ty2=(ty,ty), nty2}
// [55..74]  layer2 RY t-form q0..q9: 55 + j*2 + {tz2=(tz,tz), ntz2}
// [75]      (scale2, scale2): scale = prod_{j<5}(cx_j cy_j) * prod_j cz_j; stored squared
#define CLANE 0
#define CT    40
#define CRY   55
#define CSC   75

// ---------- gate bodies (coefficients passed in registers) ----------
// Layer-1 fused gate, full t-form: G ∝ RY_t(ty) * RX_t(tx); cos factors deferred.
__device__ __forceinline__ void tgate_body(ull* r, ull tx2, ull ty2, ull nty2,
                                           const int kb) {
#pragma unroll
    for (int m = 0; m < 8; m++) {
        if ((m >> kb) & 1) continue;
        const int m1 = m | (1 << kb);
        ull u = r[m], v = r[m1];
        ull w0 = fma2(tx2, swp(v), u);       // u - i tx v
        ull w1 = fma2(tx2, swp(u), v);       // v - i tx u
        r[m]  = fma2(nty2, w1, w0);          // w0 - ty w1
        r[m1] = fma2(ty2,  w0, w1);          // w1 + ty w0
    }
}

__device__ __forceinline__ void cshfl_body(ull* r, ull p2, ull pi2, ull q2, ull qi2,
                                           const int lb) {
#pragma unroll
    for (int k = 0; k < 8; k++) {
        float ux, uy; upk(r[k], ux, uy);
        float vx = __shfl_xor_sync(0xffffffffu, ux, 1 << lb);
        float vy = __shfl_xor_sync(0xffffffffu, uy, 1 << lb);
        r[k] = fma2(p2, r[k],
               fma2(pi2, pk(uy, ux),
               fma2(q2, pk(vx, vy), mul2(qi2, pk(vy, vx)))));
    }
}

// Layer-2 RY t-form on register bit kb (cos deferred): 2 packed ops per pair.
__device__ __forceinline__ void rgate_body(ull* r, ull tz2, ull ntz2, const int kb) {
#pragma unroll
    for (int m = 0; m < 8; m++) {
        if ((m >> kb) & 1) continue;
        const int m1 = m | (1 << kb);
        ull u = r[m], v = r[m1];
        r[m]  = fma2(ntz2, v, u);            // u - tz v
        r[m1] = fma2(tz2,  u, v);            // v + tz u
    }
}

// Layer-2 RY t-form on lane bit lb (cos deferred): 1 packed op per amplitude.
__device__ __forceinline__ void rshfl_body(ull* r, ull q2, const int lb) {
#pragma unroll
    for (int k = 0; k < 8; k++) {
        float ux, uy; upk(r[k], ux, uy);
        float vx = __shfl_xor_sync(0xffffffffu, ux, 1 << lb);
        float vy = __shfl_xor_sync(0xffffffffu, uy, 1 << lb);
        r[k] = fma2(q2, pk(vx, vy), r[k]);   // keep + (±tz) recv
    }
}

// <Z> partial reduction for one row (layout B), stores 10 values into sw[w*NW..].
__device__ __forceinline__ void zreduce(const ull* r, const int lane, const int w,
                                        float* sw) {
    float tot = 0.f, a2 = 0.f, a3 = 0.f, a4 = 0.f;
#pragma unroll
    for (int k = 0; k < 8; k++) {
        float px, py; upk(r[k], px, py);
        float pr = px * px + py * py;
        tot += pr;
        a4 += (k & 1) ? -pr : pr;   // q4 <-> bit5
        a3 += (k & 2) ? -pr : pr;   // q3 <-> bit6
        a2 += (k & 4) ? -pr : pr;   // q2 <-> bit7
    }
    float s = tot, d4, d3, d2v, d1, d0;
    {
        float n = __shfl_xor_sync(0xffffffffu, s, 16);
        d4 = (lane & 16) ? n - s : s - n; s += n;
    }
    {
        float n = __shfl_xor_sync(0xffffffffu, s, 8);
        d3 = (lane & 8) ? n - s : s - n; s += n;
        d4 += __shfl_xor_sync(0xffffffffu, d4, 8);
    }
    {
        float n = __shfl_xor_sync(0xffffffffu, s, 4);
        d2v = (lane & 4) ? n - s : s - n; s += n;
        d4 += __shfl_xor_sync(0xffffffffu, d4, 4);
        d3 += __shfl_xor_sync(0xffffffffu, d3, 4);
    }
    {
        float n = __shfl_xor_sync(0xffffffffu, s, 2);
        d1 = (lane & 2) ? n - s : s - n; s += n;
        d4 += __shfl_xor_sync(0xffffffffu, d4, 2);
        d3 += __shfl_xor_sync(0xffffffffu, d3, 2);
        d2v += __shfl_xor_sync(0xffffffffu, d2v, 2);
    }
    {
        float n = __shfl_xor_sync(0xffffffffu, s, 1);
        d0 = (lane & 1) ? n - s : s - n; s += n;
        d4 += __shfl_xor_sync(0xffffffffu, d4, 1);
        d3 += __shfl_xor_sync(0xffffffffu, d3, 1);
        d2v += __shfl_xor_sync(0xffffffffu, d2v, 1);
        d1 += __shfl_xor_sync(0xffffffffu, d1, 1);
    }
#pragma unroll
    for (int o = 16; o; o >>= 1) {
        a2 += __shfl_xor_sync(0xffffffffu, a2, o);
        a3 += __shfl_xor_sync(0xffffffffu, a3, o);
        a4 += __shfl_xor_sync(0xffffffffu, a4, o);
    }
    if (lane == 0) {
        float* p = sw + w * NW;
        p[0] = ((w >> 1) & 1) ? -s : s;   // q0 <-> bit9 (w bit1)
        p[1] = ( w       & 1) ? -s : s;   // q1 <-> bit8
        p[2] = a2;
        p[3] = a3;
        p[4] = a4;
        p[5] = d4;
        p[6] = d3;
        p[7] = d2v;
        p[8] = d1;
        p[9] = d0;
    }
}

__global__ __launch_bounds__(THREADS, 7)
void qsa_main(const float* __restrict__ x, float* __restrict__ out,
              const int nrows,
              const float* __restrict__ rx0,
              const float* __restrict__ ry0,
              const float* __restrict__ ry1) {
    __shared__ ull   buf[2][DIM];          // single 16 KB exchange buffer
    __shared__ ull   sg[76];
    __shared__ float snorm[2][2][4];       // [parity][row-in-pair][warp]
    __shared__ float swred[2][2][4 * NW];  // [parity][row-in-pair][...]

    const int t    = threadIdx.x;
    const int lane = t & 31;
    const int w    = t >> 5;

    // ---- One-time in-kernel coefficient prep (single graph node) ----
    if (t < NW) {
        float cx, sx, cy, sy, cz, sz;
        sincosf(0.5f * __ldg(rx0 + t), &sx, &cx);
        sincosf(0.5f * __ldg(ry0 + t), &sy, &cy);
        sincosf(0.5f * __ldg(ry1 + t), &sz, &cz);
        if (t >= 5) {
            // Full fused complex gate G = RY(ry0)@RX(rx0) for lane gates.
            float ar =  cx * cy, ai =  sx * sy;
            float br = -sy * cx, bi = -sx * cy;
            float cr =  sy * cx, ci = -sx * cy;
            float dr =  cx * cy, di = -sx * sy;
            ull* g = sg + CLANE + (t - 5) * 8;
            g[0] = pk(ar, ar);   g[1] = pk(-ai, ai);
            g[2] = pk(br, br);   g[3] = pk(-bi, bi);
            g[4] = pk(cr, cr);   g[5] = pk(-ci, ci);
            g[6] = pk(dr, dr);   g[7] = pk(-di, di);
        } else {
            // t-form for both RX and RY; cx*cy deferred to output scale.
            float tx = sx / cx;
            float ty = sy / cy;
            ull* g = sg + CT + t * 3;
            g[0] = pk(tx, -tx);
            g[1] = pk(ty, ty);
            g[2] = pk(-ty, -ty);
        }
        // Layer-2 RY t-form; cz deferred.
        float tz = sz / cz;
        ull* h = sg + CRY + t * 2;
        h[0] = pk(tz, tz);
        h[1] = pk(-tz, -tz);
    }
    if (t == 0) {
        float p = 1.f;
        for (int k = 0; k < 5; k++) {
            p *= cosf(0.5f * __ldg(rx0 + k));
            p *= cosf(0.5f * __ldg(ry0 + k));
        }
        for (int k = 0; k < NW; k++)
            p *= cosf(0.5f * __ldg(ry1 + k));
        sg[CSC] = pk(p * p, p * p);          // quadratic in psi -> scale^2
    }
    __syncthreads();                                       // sync0 (once)

    const int npairs = nrows >> 1;
    int prevA = -1;
    int par = 0;
    for (int pr = blockIdx.x; pr < npairs; pr += gridDim.x, par ^= 1) {
        const int rowA = 2 * pr;
        const int rowB = rowA + 1;

        // ---- Load both rows (layout A: lane=bits0-4, warp=bits5-6, k=bits7-9)
        ull rA[8], rB[8];
        float ssA = 0.f, ssB = 0.f;
        const float* xA = x + (size_t)rowA * DIM;
        const float* xB = x + (size_t)rowB * DIM;
#pragma unroll
        for (int k = 0; k < 8; k++) {
            float vA = __ldg(xA + t + THREADS * k);
            float vB = __ldg(xB + t + THREADS * k);
            rA[k] = pk(vA, 0.f);  ssA += vA * vA;
            rB[k] = pk(vB, 0.f);  ssB += vB * vB;
        }
#pragma unroll
        for (int o = 16; o; o >>= 1) {
            ssA += __shfl_xor_sync(0xffffffffu, ssA, o);
            ssB += __shfl_xor_sync(0xffffffffu, ssB, o);
        }
        if (lane == 0) { snorm[par][0][w] = ssA; snorm[par][1][w] = ssB; }

        // ======== Layer 1: t-gates on reg bits, complex gates on lane bits ====
#pragma unroll
        for (int j = 0; j < 3; j++) {                     // q0,q1,q2 -> kb 2,1,0
            const ull* g = sg + CT + 3 * j;
            ull tx2 = g[0], ty2 = g[1], nty2 = g[2];
            tgate_body(rA, tx2, ty2, nty2, 2 - j);
            tgate_body(rB, tx2, ty2, nty2, 2 - j);
        }
#pragma unroll
        for (int j = 0; j < 5; j++) {                     // q5..q9 -> lb 4..0
            const ull* g = sg + CLANE + 8 * j;
            const int lb = 4 - j;
            const bool hi = (lane >> lb) & 1;
            ull p2  = hi ? g[6] : g[0];
            ull pi2 = hi ? g[7] : g[1];
            ull q2  = hi ? g[4] : g[2];
            ull qi2 = hi ? g[5] : g[3];
            cshfl_body(rA, p2, pi2, q2, qi2, lb);
            cshfl_body(rB, p2, pi2, q2, qi2, lb);
        }

        // WAR guard: prior iteration's buf reads must finish before overwrite.
        __syncthreads();                                   // syncP

        // ---- Exchange 1: A -> B layout (i = lane | (k<<5) | (w<<8)) ----
#pragma unroll
        for (int k = 0; k < 8; k++) {
            buf[0][t + THREADS * k] = rA[k];
            buf[1][t + THREADS * k] = rB[k];
        }
        __syncthreads();                                   // sync1
#pragma unroll
        for (int k = 0; k < 8; k++) {
            const int idx = lane | (k << 5) | (w << 8);
            rA[k] = buf[0][idx];
            rB[k] = buf[1][idx];
        }

        // ---- Software-pipelined output of the PREVIOUS pair ----
        if (prevA >= 0) {
            const int q = par ^ 1;
            float sc, dmy; upk(sg[CSC], sc, dmy);
            if (t < NW) {
                const float* sn = snorm[q][0];
                float s = sn[0] + sn[1] + sn[2] + sn[3];
                const float* sw = swred[q][0];
                float e = sw[t] + sw[NW + t] + sw[2 * NW + t] + sw[3 * NW + t];
                out[(size_t)prevA * NW + t] = e * sc / fmaxf(s, 1e-24f);
            } else if (t >= 32 && t < 32 + NW) {
                const int tt = t - 32;
                const float* sn = snorm[q][1];
                float s = sn[0] + sn[1] + sn[2] + sn[3];
                const float* sw = swred[q][1];
                float e = sw[tt] + sw[NW + tt] + sw[2 * NW + tt] + sw[3 * NW + tt];
                out[(size_t)(prevA + 1) * NW + tt] = e * sc / fmaxf(s, 1e-24f);
            }
        }

        // q4 (kb0), q3 (kb1) t-gates in layout B
        {
            const ull* g = sg + CT + 3 * 4;
            tgate_body(rA, g[0], g[1], g[2], 0);
            tgate_body(rB, g[0], g[1], g[2], 0);
        }
        {
            const ull* g = sg + CT + 3 * 3;
            tgate_body(rA, g[0], g[1], g[2], 1);
            tgate_body(rB, g[0], g[1], g[2], 1);
        }

        __syncthreads();                                   // sync1w (WAR on buf)

        // ---- Exchange 2: CNOT ring (suffix-XOR permutation) -> layout A ----
#pragma unroll
        for (int k = 0; k < 8; k++) {
            unsigned i = (unsigned)(lane | (k << 5) | (w << 8));
            unsigned y = i;
            y ^= y >> 1; y ^= y >> 2; y ^= y >> 4; y ^= y >> 8;
            unsigned dst = (y & 0x1FFu) | (((y ^ (i >> 9)) & 1u) << 9);
            buf[0][dst] = rA[k];
            buf[1][dst] = rB[k];
        }
        __syncthreads();                                   // sync2
#pragma unroll
        for (int k = 0; k < 8; k++) {
            rA[k] = buf[0][t + THREADS * k];
            rB[k] = buf[1][t + THREADS * k];
        }

        // ======== Layer 2 (RY t-form, cos deferred) ========
#pragma unroll
        for (int j = 0; j < 3; j++) {                     // q0,q1,q2 -> kb 2,1,0
            const ull* g = sg + CRY + 2 * j;
            rgate_body(rA, g[0], g[1], 2 - j);
            rgate_body(rB, g[0], g[1], 2 - j);
        }
#pragma unroll
        for (int j = 5; j < 10; j++) {                    // q5..q9 -> lb 4..0
            const ull* g = sg + CRY + 2 * j;
            const int lb = 9 - j;
            const bool hi = (lane >> lb) & 1;
            ull q2 = hi ? g[0] : g[1];                    // +tz / -tz
            rshfl_body(rA, q2, lb);
            rshfl_body(rB, q2, lb);
        }

        __syncthreads();                                   // sync2w (WAR on buf)

        // ---- Exchange 3: A -> B layout ----
#pragma unroll
        for (int k = 0; k < 8; k++) {
            buf[0][t + THREADS * k] = rA[k];
            buf[1][t + THREADS * k] = rB[k];
        }
        __syncthreads();                                   // sync3
#pragma unroll
        for (int k = 0; k < 8; k++) {
            const int idx = lane | (k << 5) | (w << 8);
            rA[k] = buf[0][idx];
            rB[k] = buf[1][idx];
        }
        {
            const ull* g = sg + CRY + 2 * 4;               // q4 (kb0)
            rgate_body(rA, g[0], g[1], 0);
            rgate_body(rB, g[0], g[1], 0);
        }
        {
            const ull* g = sg + CRY + 2 * 3;               // q3 (kb1)
            rgate_body(rA, g[0], g[1], 1);
            rgate_body(rB, g[0], g[1], 1);
        }

        // ======== <Z_j> reductions into parity slot (read next iteration) ====
        zreduce(rA, lane, w, swred[par][0]);
        zreduce(rB, lane, w, swred[par][1]);

        prevA = rowA;
    }

    // ---- Final pair output (one trailing barrier makes all writes visible) ----
    __syncthreads();
    if (prevA >= 0) {
        const int q = par ^ 1;          // parity slot of the last iteration
        float sc, dmy; upk(sg[CSC], sc, dmy);
        if (t < NW) {
            const float* sn = snorm[q][0];
            float s = sn[0] + sn[1] + sn[2] + sn[3];
            const float* sw = swred[q][0];
            float e = sw[t] + sw[NW + t] + sw[2 * NW + t] + sw[3 * NW + t];
            out[(size_t)prevA * NW + t] = e * sc / fmaxf(s, 1e-24f);
        } else if (t >= 32 && t < 32 + NW) {
            const int tt = t - 32;
            const float* sn = snorm[q][1];
            float s = sn[0] + sn[1] + sn[2] + sn[3];
            const float* sw = swred[q][1];
            float e = sw[tt] + sw[NW + tt] + sw[2 * NW + tt] + sw[3 * NW + tt];
            out[(size_t)(prevA + 1) * NW + tt] = e * sc / fmaxf(s, 1e-24f);
        }
    }
}

extern "C" void kernel_launch(void* const* d_in, const int* in_sizes, int n_in,
                              void* d_out, int out_size) {
    const float* x   = (const float*)d_in[0];
    const float* rx0 = (const float*)d_in[1];
    const float* ry0 = (const float*)d_in[2];
    const float* ry1 = (const float*)d_in[3];
    float* out = (float*)d_out;

    int nrows = in_sizes[0] / DIM;  // 4096
    int npairs = nrows >> 1;        // 2048

    // ~17 KB smem + <=72 regs -> 7 CTAs/SM -> capacity 1036 >= 1024:
    // single wave, every CTA runs exactly 2 pair-iterations.
    int grid = 1024;
    if (grid > npairs) grid = npairs;
    qsa_main<<<grid, THREADS>>>(x, out, nrows, rx0, ry0, ry1);
}

// round 16
// speedup vs baseline: 1.0077x; 1.0077x over previous
#include <cuda_runtime.h>

#define NW      10
#define DIM     1024
#define THREADS 128

typedef unsigned long long ull;

// ---------- packed f32x2 helpers ----------
__device__ __forceinline__ ull pk(float lo, float hi) {
    ull r;
    asm("mov.b64 %0, {%1, %2};" : "=l"(r)
        : "r"(__float_as_uint(lo)), "r"(__float_as_uint(hi)));
    return r;
}
__device__ __forceinline__ void upk(ull v, float& lo, float& hi) {
    unsigned a, b;
    asm("mov.b64 {%0, %1}, %2;" : "=r"(a), "=r"(b) : "l"(v));
    lo = __uint_as_float(a); hi = __uint_as_float(b);
}
__device__ __forceinline__ ull swp(ull v) {
    float lo, hi; upk(v, lo, hi); return pk(hi, lo);
}
__device__ __forceinline__ ull fma2(ull a, ull b, ull c) {
    ull d;
    asm("fma.rn.f32x2 %0, %1, %2, %3;" : "=l"(d) : "l"(a), "l"(b), "l"(c));
    return d;
}
__device__ __forceinline__ ull mul2(ull a, ull b) {
    ull d;
    asm("mul.rn.f32x2 %0, %1, %2;" : "=l"(d) : "l"(a), "l"(b));
    return d;
}

// smem coefficient bank layout (ull indices):
// [ 0..39] lane complex gates q5..q9: (j-5)*8 + {a2 ai2 b2 bi2 c2 ci2 d2 di2}
// [40..59] layer1 t-gates q0..q4: 40 + j*4 + {t2=(tx,-tx), c2=(cy,cy), s2, ns2}
//          (RX in t-form, cos(rx/2) deferred; RY full)
// [60..99] layer2 RY q0..q9: 60 + j*4 + {c2, s2, ns2, pad}
#define CLANE 0
#define CT    40
#define CRY   60

// ---------- gate bodies ----------
// Layer-1 fused gate: (I - i tx X) then full RY(ry0). 6 packed ops per pair.
__device__ __forceinline__ void tgate_body(ull* r, ull t2, ull c2, ull s2, ull ns2,
                                           const int kb) {
#pragma unroll
    for (int m = 0; m < 8; m++) {
        if ((m >> kb) & 1) continue;
        const int m1 = m | (1 << kb);
        ull u = r[m], v = r[m1];
        ull w0 = fma2(t2, swp(v), u);        // u - i tx v
        ull w1 = fma2(t2, swp(u), v);        // v - i tx u
        r[m]  = fma2(c2, w0, mul2(ns2, w1));
        r[m1] = fma2(c2, w1, mul2(s2,  w0));
    }
}

__device__ __forceinline__ void cshfl_body(ull* r, ull p2, ull pi2, ull q2, ull qi2,
                                           const int lb) {
#pragma unroll
    for (int k = 0; k < 8; k++) {
        float ux, uy; upk(r[k], ux, uy);
        float vx = __shfl_xor_sync(0xffffffffu, ux, 1 << lb);
        float vy = __shfl_xor_sync(0xffffffffu, uy, 1 << lb);
        r[k] = fma2(p2, r[k],
               fma2(pi2, pk(uy, ux),
               fma2(q2, pk(vx, vy), mul2(qi2, pk(vy, vx)))));
    }
}

// Layer-2 full RY on register bit kb.
__device__ __forceinline__ void rgate_body(ull* r, ull c2, ull s2, ull ns2,
                                           const int kb) {
#pragma unroll
    for (int m = 0; m < 8; m++) {
        if ((m >> kb) & 1) continue;
        const int m1 = m | (1 << kb);
        ull u = r[m], v = r[m1];
        r[m]  = fma2(c2, u, mul2(ns2, v));
        r[m1] = fma2(c2, v, mul2(s2, u));
    }
}

// Layer-2 full RY on lane bit lb.
__device__ __forceinline__ void rshfl_body(ull* r, ull c2, ull q2, const int lb) {
#pragma unroll
    for (int k = 0; k < 8; k++) {
        float ux, uy; upk(r[k], ux, uy);
        float vx = __shfl_xor_sync(0xffffffffu, ux, 1 << lb);
        float vy = __shfl_xor_sync(0xffffffffu, uy, 1 << lb);
        r[k] = fma2(c2, r[k], mul2(q2, pk(vx, vy)));
    }
}

// <Z> partial reduction (layout B). Stores 10 signed sums + unsigned total
// (stride 12) into sw[w*12 ..]. out_j = (sum_w sw[j]) / (sum_w sw[10]).
__device__ __forceinline__ void zreduce(const ull* r, const int lane, const int w,
                                        float* sw) {
    float tot = 0.f, a2 = 0.f, a3 = 0.f, a4 = 0.f;
#pragma unroll
    for (int k = 0; k < 8; k++) {
        float px, py; upk(r[k], px, py);
        float pr = px * px + py * py;
        tot += pr;
        a4 += (k & 1) ? -pr : pr;   // q4 <-> bit5
        a3 += (k & 2) ? -pr : pr;   // q3 <-> bit6
        a2 += (k & 4) ? -pr : pr;   // q2 <-> bit7
    }
    float s = tot, d4, d3, d2v, d1, d0;
    {
        float n = __shfl_xor_sync(0xffffffffu, s, 16);
        d4 = (lane & 16) ? n - s : s - n; s += n;
    }
    {
        float n = __shfl_xor_sync(0xffffffffu, s, 8);
        d3 = (lane & 8) ? n - s : s - n; s += n;
        d4 += __shfl_xor_sync(0xffffffffu, d4, 8);
    }
    {
        float n = __shfl_xor_sync(0xffffffffu, s, 4);
        d2v = (lane & 4) ? n - s : s - n; s += n;
        d4 += __shfl_xor_sync(0xffffffffu, d4, 4);
        d3 += __shfl_xor_sync(0xffffffffu, d3, 4);
    }
    {
        float n = __shfl_xor_sync(0xffffffffu, s, 2);
        d1 = (lane & 2) ? n - s : s - n; s += n;
        d4 += __shfl_xor_sync(0xffffffffu, d4, 2);
        d3 += __shfl_xor_sync(0xffffffffu, d3, 2);
        d2v += __shfl_xor_sync(0xffffffffu, d2v, 2);
    }
    {
        float n = __shfl_xor_sync(0xffffffffu, s, 1);
        d0 = (lane & 1) ? n - s : s - n; s += n;
        d4 += __shfl_xor_sync(0xffffffffu, d4, 1);
        d3 += __shfl_xor_sync(0xffffffffu, d3, 1);
        d2v += __shfl_xor_sync(0xffffffffu, d2v, 1);
        d1 += __shfl_xor_sync(0xffffffffu, d1, 1);
    }
#pragma unroll
    for (int o = 16; o; o >>= 1) {
        a2 += __shfl_xor_sync(0xffffffffu, a2, o);
        a3 += __shfl_xor_sync(0xffffffffu, a3, o);
        a4 += __shfl_xor_sync(0xffffffffu, a4, o);
    }
    if (lane == 0) {
        float* p = sw + w * 12;
        p[0]  = ((w >> 1) & 1) ? -s : s;   // q0 <-> bit9 (w bit1)
        p[1]  = ( w       & 1) ? -s : s;   // q1 <-> bit8
        p[2]  = a2;
        p[3]  = a3;
        p[4]  = a4;
        p[5]  = d4;
        p[6]  = d3;
        p[7]  = d2v;
        p[8]  = d1;
        p[9]  = d0;
        p[10] = s;                         // unsigned total (for normalization)
    }
}

__global__ __launch_bounds__(THREADS, 8)
void qsa_main(const float* __restrict__ x, float* __restrict__ out,
              const int nrows, const int rpc,
              const float* __restrict__ rx0,
              const float* __restrict__ ry0,
              const float* __restrict__ ry1) {
    __shared__ ull   buf0[DIM];
    __shared__ ull   buf1[DIM];
    __shared__ ull   sg[100];
    __shared__ float swred[4][4 * 12];     // 4-deep rotation, stride 12 per warp

    const int t    = threadIdx.x;
    const int lane = t & 31;
    const int w    = t >> 5;

    // ---- One-time in-kernel coefficient prep (single graph node) ----
    if (t < NW) {
        float cx, sx, cy, sy, cz, sz;
        sincosf(0.5f * __ldg(rx0 + t), &sx, &cx);
        sincosf(0.5f * __ldg(ry0 + t), &sy, &cy);
        sincosf(0.5f * __ldg(ry1 + t), &sz, &cz);
        if (t >= 5) {
            // Full fused complex gate G = RY(ry0)@RX(rx0) for lane gates.
            float ar =  cx * cy, ai =  sx * sy;
            float br = -sy * cx, bi = -sx * cy;
            float cr =  sy * cx, ci = -sx * cy;
            float dr =  cx * cy, di = -sx * sy;
            ull* g = sg + CLANE + (t - 5) * 8;
            g[0] = pk(ar, ar);   g[1] = pk(-ai, ai);
            g[2] = pk(br, br);   g[3] = pk(-bi, bi);
            g[4] = pk(cr, cr);   g[5] = pk(-ci, ci);
            g[6] = pk(dr, dr);   g[7] = pk(-di, di);
        } else {
            // RX t-form (cos deferred; normalization cancels it), RY full.
            float tx = sx / cx;
            ull* g = sg + CT + t * 4;
            g[0] = pk(tx, -tx);
            g[1] = pk(cy, cy);
            g[2] = pk(sy, sy);
            g[3] = pk(-sy, -sy);
        }
        ull* h = sg + CRY + t * 4;
        h[0] = pk(cz, cz);   h[1] = pk(sz, sz);   h[2] = pk(-sz, -sz);
        h[3] = 0;
    }
    __syncthreads();                                       // sync0 (once)

    const int base = blockIdx.x * rpc;
    int prev = -1;
    int it = 0;
    for (; it < rpc; it++) {
        const int row = base + it;
        if (row >= nrows) break;
        // Parity-alternating buffers: exchanges use exb, CNOT scatter uses cnb.
        // Cross-iteration reuse of each buffer is fenced by an interleaved
        // barrier (exb(n+1) write vs cnb... see analysis) -> race-free at
        // 3 barriers/row.
        ull* exb = (it & 1) ? buf1 : buf0;
        ull* cnb = (it & 1) ? buf0 : buf1;

        // ---- Load (layout A: i = t + 128k; lane=bits0-4, warp=bits5-6, k=bits7-9)
        // No norm reduction: unitarity makes out = e/tot.
        ull r[8];
        const float* xr = x + (size_t)row * DIM;
#pragma unroll
        for (int k = 0; k < 8; k++)
            r[k] = pk(__ldg(xr + t + THREADS * k), 0.f);

        // ======== Layer 1 ========
#pragma unroll
        for (int j = 0; j < 3; j++) {                     // q0,q1,q2 -> kb 2,1,0
            const ull* g = sg + CT + 4 * j;
            tgate_body(r, g[0], g[1], g[2], g[3], 2 - j);
        }
#pragma unroll
        for (int j = 0; j < 5; j++) {                     // q5..q9 -> lb 4..0
            const ull* g = sg + CLANE + 8 * j;
            const int lb = 4 - j;
            const bool hi = (lane >> lb) & 1;
            ull p2  = hi ? g[6] : g[0];
            ull pi2 = hi ? g[7] : g[1];
            ull q2  = hi ? g[4] : g[2];
            ull qi2 = hi ? g[5] : g[3];
            cshfl_body(r, p2, pi2, q2, qi2, lb);
        }

        // ---- Exchange 1: A -> B layout (i = lane | (k<<5) | (w<<8)) ----
#pragma unroll
        for (int k = 0; k < 8; k++) exb[t + THREADS * k] = r[k];
        __syncthreads();                                   // sync1
#pragma unroll
        for (int k = 0; k < 8; k++) r[k] = exb[lane | (k << 5) | (w << 8)];

        // ---- Software-pipelined output of the PREVIOUS row (ordered by sync1;
        // rotation slot untouched until iteration prev+4). ----
        if (prev >= 0 && t < NW) {
            const float* sw = swred[(it - 1) & 3];
            float e   = sw[t]      + sw[12 + t]      + sw[24 + t]      + sw[36 + t];
            float tot = sw[10]     + sw[12 + 10]     + sw[24 + 10]     + sw[36 + 10];
            out[(size_t)prev * NW + t] = e / fmaxf(tot, 1e-30f);
        }

        // q4 (kb0), q3 (kb1) layer-1 gates in layout B
        {
            const ull* g = sg + CT + 4 * 4;
            tgate_body(r, g[0], g[1], g[2], g[3], 0);
        }
        {
            const ull* g = sg + CT + 4 * 3;
            tgate_body(r, g[0], g[1], g[2], g[3], 1);
        }

        // ---- Exchange 2: CNOT ring (suffix-XOR permutation) -> layout A ----
#pragma unroll
        for (int k = 0; k < 8; k++) {
            unsigned i = (unsigned)(lane | (k << 5) | (w << 8));
            unsigned y = i;
            y ^= y >> 1; y ^= y >> 2; y ^= y >> 4; y ^= y >> 8;
            unsigned dst = (y & 0x1FFu) | (((y ^ (i >> 9)) & 1u) << 9);
            cnb[dst] = r[k];
        }
        __syncthreads();                                   // sync2
#pragma unroll
        for (int k = 0; k < 8; k++) r[k] = cnb[t + THREADS * k];

        // ======== Layer 2 (full RY) ========
#pragma unroll
        for (int j = 0; j < 3; j++) {                     // q0,q1,q2 -> kb 2,1,0
            const ull* g = sg + CRY + 4 * j;
            rgate_body(r, g[0], g[1], g[2], 2 - j);
        }
#pragma unroll
        for (int j = 5; j < 10; j++) {                    // q5..q9 -> lb 4..0
            const ull* g = sg + CRY + 4 * j;
            const int lb = 9 - j;
            const bool hi = (lane >> lb) & 1;
            ull q2 = hi ? g[1] : g[2];
            rshfl_body(r, g[0], q2, lb);
        }

        // ---- Exchange 3: A -> B layout (same exb; fenced by sync2) ----
#pragma unroll
        for (int k = 0; k < 8; k++) exb[t + THREADS * k] = r[k];
        __syncthreads();                                   // sync3
#pragma unroll
        for (int k = 0; k < 8; k++) r[k] = exb[lane | (k << 5) | (w << 8)];

        {
            const ull* g = sg + CRY + 4 * 4;               // q4 (kb0)
            rgate_body(r, g[0], g[1], g[2], 0);
        }
        {
            const ull* g = sg + CRY + 4 * 3;               // q3 (kb1)
            rgate_body(r, g[0], g[1], g[2], 1);
        }

        // ======== <Z_j> reduction into rotation slot (read next iteration) ====
        zreduce(r, lane, w, swred[it & 3]);

        prev = row;
    }

    // ---- Final row output (one trailing barrier makes all writes visible) ----
    __syncthreads();
    if (prev >= 0 && t < NW) {
        const float* sw = swred[(it - 1) & 3];
        float e   = sw[t]      + sw[12 + t]      + sw[24 + t]      + sw[36 + t];
        float tot = sw[10]     + sw[12 + 10]     + sw[24 + 10]     + sw[36 + 10];
        out[(size_t)prev * NW + t] = e / fmaxf(tot, 1e-30f);
    }
}

extern "C" void kernel_launch(void* const* d_in, const int* in_sizes, int n_in,
                              void* d_out, int out_size) {
    const float* x   = (const float*)d_in[0];
    const float* rx0 = (const float*)d_in[1];
    const float* ry0 = (const float*)d_in[2];
    const float* ry1 = (const float*)d_in[3];
    float* out = (float*)d_out;

    int nrows = in_sizes[0] / DIM;  // 4096

    // 8 CTAs/SM (regs<=64, smem ~17.6 KB) x 148 SMs = 1184 capacity >= 1024:
    // single wave; each CTA processes 4 contiguous rows.
    int grid = 1024;
    if (grid > nrows) grid = nrows;
    int rpc = (nrows + grid - 1) / grid;   // 4 for nrows=4096
    qsa_main<<<grid, THREADS>>>(x, out, nrows, rpc, rx0, ry0, ry1);
}

// round 17
// speedup vs baseline: 1.0738x; 1.0656x over previous
#include <cuda_runtime.h>

#define NW      10
#define DIM     1024
#define THREADS 128

typedef unsigned long long ull;

// ---------- packed f32x2 helpers ----------
__device__ __forceinline__ ull pk(float lo, float hi) {
    ull r;
    asm("mov.b64 %0, {%1, %2};" : "=l"(r)
        : "r"(__float_as_uint(lo)), "r"(__float_as_uint(hi)));
    return r;
}
__device__ __forceinline__ void upk(ull v, float& lo, float& hi) {
    unsigned a, b;
    asm("mov.b64 {%0, %1}, %2;" : "=r"(a), "=r"(b) : "l"(v));
    lo = __uint_as_float(a); hi = __uint_as_float(b);
}
__device__ __forceinline__ ull swp(ull v) {
    float lo, hi; upk(v, lo, hi); return pk(hi, lo);
}
__device__ __forceinline__ ull fma2(ull a, ull b, ull c) {
    ull d;
    asm("fma.rn.f32x2 %0, %1, %2, %3;" : "=l"(d) : "l"(a), "l"(b), "l"(c));
    return d;
}
__device__ __forceinline__ ull mul2(ull a, ull b) {
    ull d;
    asm("mul.rn.f32x2 %0, %1, %2;" : "=l"(d) : "l"(a), "l"(b));
    return d;
}

// smem coefficient bank layout (ull indices):
// [ 0..39]  lane complex gates q5..q9: (j-5)*8 + {a2 ai2 b2 bi2 c2 ci2 d2 di2}
// [40..59]  t-gates q0..q4 layer1: 40 + j*4 + {t2=(tx,-tx), c2=(cy,cy), s2, ns2}
//           (RX t-form, cos deferred — cancelled by unitarity normalization)
// [60..99]  layer2 RY q0..q9: 60 + j*4 + {c2, s2, ns2, pad}
#define CLANE 0
#define CT    40
#define CRY   60

// ---------- gate bodies (coefficients passed in registers) ----------
__device__ __forceinline__ void tgate_body(ull* r, ull t2, ull c2, ull s2, ull ns2,
                                           const int kb) {
#pragma unroll
    for (int m = 0; m < 8; m++) {
        if ((m >> kb) & 1) continue;
        const int m1 = m | (1 << kb);
        ull u = r[m], v = r[m1];
        ull w0 = fma2(t2, swp(v), u);
        ull w1 = fma2(t2, swp(u), v);
        r[m]  = fma2(c2, w0, mul2(ns2, w1));
        r[m1] = fma2(c2, w1, mul2(s2,  w0));
    }
}

__device__ __forceinline__ void cshfl_body(ull* r, ull p2, ull pi2, ull q2, ull qi2,
                                           const int lb) {
#pragma unroll
    for (int k = 0; k < 8; k++) {
        float ux, uy; upk(r[k], ux, uy);
        float vx = __shfl_xor_sync(0xffffffffu, ux, 1 << lb);
        float vy = __shfl_xor_sync(0xffffffffu, uy, 1 << lb);
        r[k] = fma2(p2, r[k],
               fma2(pi2, pk(uy, ux),
               fma2(q2, pk(vx, vy), mul2(qi2, pk(vy, vx)))));
    }
}

__device__ __forceinline__ void rgate_body(ull* r, ull c2, ull s2, ull ns2,
                                           const int kb) {
#pragma unroll
    for (int m = 0; m < 8; m++) {
        if ((m >> kb) & 1) continue;
        const int m1 = m | (1 << kb);
        ull u = r[m], v = r[m1];
        r[m]  = fma2(c2, u, mul2(ns2, v));
        r[m1] = fma2(c2, v, mul2(s2, u));
    }
}

__device__ __forceinline__ void rshfl_body(ull* r, ull c2, ull q2, const int lb) {
#pragma unroll
    for (int k = 0; k < 8; k++) {
        float ux, uy; upk(r[k], ux, uy);
        float vx = __shfl_xor_sync(0xffffffffu, ux, 1 << lb);
        float vy = __shfl_xor_sync(0xffffffffu, uy, 1 << lb);
        r[k] = fma2(c2, r[k], mul2(q2, pk(vx, vy)));
    }
}

// <Z> partial reduction for one row (layout B). Stores 10 signed sums plus the
// unsigned total (slot 10, stride 12) into sw[w*12..]. out = e / tot.
__device__ __forceinline__ void zreduce(const ull* r, const int lane, const int w,
                                        float* sw) {
    float tot = 0.f, a2 = 0.f, a3 = 0.f, a4 = 0.f;
#pragma unroll
    for (int k = 0; k < 8; k++) {
        float px, py; upk(r[k], px, py);
        float pr = px * px + py * py;
        tot += pr;
        a4 += (k & 1) ? -pr : pr;   // q4 <-> bit5
        a3 += (k & 2) ? -pr : pr;   // q3 <-> bit6
        a2 += (k & 4) ? -pr : pr;   // q2 <-> bit7
    }
    float s = tot, d4, d3, d2v, d1, d0;
    {
        float n = __shfl_xor_sync(0xffffffffu, s, 16);
        d4 = (lane & 16) ? n - s : s - n; s += n;
    }
    {
        float n = __shfl_xor_sync(0xffffffffu, s, 8);
        d3 = (lane & 8) ? n - s : s - n; s += n;
        d4 += __shfl_xor_sync(0xffffffffu, d4, 8);
    }
    {
        float n = __shfl_xor_sync(0xffffffffu, s, 4);
        d2v = (lane & 4) ? n - s : s - n; s += n;
        d4 += __shfl_xor_sync(0xffffffffu, d4, 4);
        d3 += __shfl_xor_sync(0xffffffffu, d3, 4);
    }
    {
        float n = __shfl_xor_sync(0xffffffffu, s, 2);
        d1 = (lane & 2) ? n - s : s - n; s += n;
        d4 += __shfl_xor_sync(0xffffffffu, d4, 2);
        d3 += __shfl_xor_sync(0xffffffffu, d3, 2);
        d2v += __shfl_xor_sync(0xffffffffu, d2v, 2);
    }
    {
        float n = __shfl_xor_sync(0xffffffffu, s, 1);
        d0 = (lane & 1) ? n - s : s - n; s += n;
        d4 += __shfl_xor_sync(0xffffffffu, d4, 1);
        d3 += __shfl_xor_sync(0xffffffffu, d3, 1);
        d2v += __shfl_xor_sync(0xffffffffu, d2v, 1);
        d1 += __shfl_xor_sync(0xffffffffu, d1, 1);
    }
#pragma unroll
    for (int o = 16; o; o >>= 1) {
        a2 += __shfl_xor_sync(0xffffffffu, a2, o);
        a3 += __shfl_xor_sync(0xffffffffu, a3, o);
        a4 += __shfl_xor_sync(0xffffffffu, a4, o);
    }
    if (lane == 0) {
        float* p = sw + w * 12;
        p[0]  = ((w >> 1) & 1) ? -s : s;   // q0 <-> bit9 (w bit1)
        p[1]  = ( w       & 1) ? -s : s;   // q1 <-> bit8
        p[2]  = a2;
        p[3]  = a3;
        p[4]  = a4;
        p[5]  = d4;
        p[6]  = d3;
        p[7]  = d2v;
        p[8]  = d1;
        p[9]  = d0;
        p[10] = s;                         // unsigned total (normalization)
    }
}

__global__ __launch_bounds__(THREADS, 8)
void qsa_main(const float* __restrict__ x, float* __restrict__ out,
              const int nrows,
              const float* __restrict__ rx0,
              const float* __restrict__ ry0,
              const float* __restrict__ ry1) {
    __shared__ ull   buf[2][DIM];          // single 16 KB exchange buffer
    __shared__ ull   sg[100];
    __shared__ float swred[2][2][4 * 12];  // [parity][row-in-pair][warp*12]

    const int t    = threadIdx.x;
    const int lane = t & 31;
    const int w    = t >> 5;

    // ---- One-time in-kernel coefficient prep (single graph node) ----
    if (t < NW) {
        float cx, sx, cy, sy, cz, sz;
        sincosf(0.5f * __ldg(rx0 + t), &sx, &cx);
        sincosf(0.5f * __ldg(ry0 + t), &sy, &cy);
        sincosf(0.5f * __ldg(ry1 + t), &sz, &cz);
        if (t >= 5) {
            float ar =  cx * cy, ai =  sx * sy;
            float br = -sy * cx, bi = -sx * cy;
            float cr =  sy * cx, ci = -sx * cy;
            float dr =  cx * cy, di = -sx * sy;
            ull* g = sg + CLANE + (t - 5) * 8;
            g[0] = pk(ar, ar);   g[1] = pk(-ai, ai);
            g[2] = pk(br, br);   g[3] = pk(-bi, bi);
            g[4] = pk(cr, cr);   g[5] = pk(-ci, ci);
            g[6] = pk(dr, dr);   g[7] = pk(-di, di);
        } else {
            float tt = sx / cx;          // tan(rx0/2); cos deferred (cancels)
            ull* g = sg + CT + t * 4;
            g[0] = pk(tt, -tt);
            g[1] = pk(cy, cy);
            g[2] = pk(sy, sy);
            g[3] = pk(-sy, -sy);
        }
        ull* h = sg + CRY + t * 4;
        h[0] = pk(cz, cz);   h[1] = pk(sz, sz);   h[2] = pk(-sz, -sz);
        h[3] = 0;
    }
    __syncthreads();                                       // sync0 (once)

    const int npairs = nrows >> 1;
    int prevA = -1;
    int par = 0;
    for (int pr = blockIdx.x; pr < npairs; pr += gridDim.x, par ^= 1) {
        const int rowA = 2 * pr;
        const int rowB = rowA + 1;

        // ---- Load both rows (layout A: lane=bits0-4, warp=bits5-6, k=bits7-9)
        // No norm reduction: unitarity gives out = e/tot from zreduce.
        ull rA[8], rB[8];
        const float* xA = x + (size_t)rowA * DIM;
        const float* xB = x + (size_t)rowB * DIM;
#pragma unroll
        for (int k = 0; k < 8; k++) {
            rA[k] = pk(__ldg(xA + t + THREADS * k), 0.f);
            rB[k] = pk(__ldg(xB + t + THREADS * k), 0.f);
        }

        // ======== Layer 1: t-gates on reg bits, complex gates on lane bits ====
#pragma unroll
        for (int j = 0; j < 3; j++) {                     // q0,q1,q2 -> kb 2,1,0
            const ull* g = sg + CT + 4 * j;
            ull t2 = g[0], c2 = g[1], s2 = g[2], ns2 = g[3];
            tgate_body(rA, t2, c2, s2, ns2, 2 - j);
            tgate_body(rB, t2, c2, s2, ns2, 2 - j);
        }
#pragma unroll
        for (int j = 0; j < 5; j++) {                     // q5..q9 -> lb 4..0
            const ull* g = sg + CLANE + 8 * j;
            const int lb = 4 - j;
            const bool hi = (lane >> lb) & 1;
            ull p2  = hi ? g[6] : g[0];
            ull pi2 = hi ? g[7] : g[1];
            ull q2  = hi ? g[4] : g[2];
            ull qi2 = hi ? g[5] : g[3];
            cshfl_body(rA, p2, pi2, q2, qi2, lb);
            cshfl_body(rB, p2, pi2, q2, qi2, lb);
        }

        // WAR guard: prior iteration's buf reads must finish before overwrite.
        __syncthreads();                                   // syncP

        // ---- Exchange 1: A -> B layout (i = lane | (k<<5) | (w<<8)) ----
#pragma unroll
        for (int k = 0; k < 8; k++) {
            buf[0][t + THREADS * k] = rA[k];
            buf[1][t + THREADS * k] = rB[k];
        }
        __syncthreads();                                   // sync1
#pragma unroll
        for (int k = 0; k < 8; k++) {
            const int idx = lane | (k << 5) | (w << 8);
            rA[k] = buf[0][idx];
            rB[k] = buf[1][idx];
        }

        // ---- Software-pipelined output of the PREVIOUS pair ----
        if (prevA >= 0) {
            const int q = par ^ 1;
            if (t < NW) {
                const float* sw = swred[q][0];
                float e   = sw[t]  + sw[12 + t]  + sw[24 + t]  + sw[36 + t];
                float tot = sw[10] + sw[12 + 10] + sw[24 + 10] + sw[36 + 10];
                out[(size_t)prevA * NW + t] = e / fmaxf(tot, 1e-30f);
            } else if (t >= 32 && t < 32 + NW) {
                const int tt = t - 32;
                const float* sw = swred[q][1];
                float e   = sw[tt] + sw[12 + tt] + sw[24 + tt] + sw[36 + tt];
                float tot = sw[10] + sw[12 + 10] + sw[24 + 10] + sw[36 + 10];
                out[(size_t)(prevA + 1) * NW + tt] = e / fmaxf(tot, 1e-30f);
            }
        }

        // q4 (kb0), q3 (kb1) t-gates in layout B
        {
            const ull* g = sg + CT + 4 * 4;
            ull t2 = g[0], c2 = g[1], s2 = g[2], ns2 = g[3];
            tgate_body(rA, t2, c2, s2, ns2, 0);
            tgate_body(rB, t2, c2, s2, ns2, 0);
        }
        {
            const ull* g = sg + CT + 4 * 3;
            ull t2 = g[0], c2 = g[1], s2 = g[2], ns2 = g[3];
            tgate_body(rA, t2, c2, s2, ns2, 1);
            tgate_body(rB, t2, c2, s2, ns2, 1);
        }

        __syncthreads();                                   // sync1w (WAR on buf)

        // ---- Exchange 2: CNOT ring (suffix-XOR permutation) -> layout A ----
#pragma unroll
        for (int k = 0; k < 8; k++) {
            unsigned i = (unsigned)(lane | (k << 5) | (w << 8));
            unsigned y = i;
            y ^= y >> 1; y ^= y >> 2; y ^= y >> 4; y ^= y >> 8;
            unsigned dst = (y & 0x1FFu) | (((y ^ (i >> 9)) & 1u) << 9);
            buf[0][dst] = rA[k];
            buf[1][dst] = rB[k];
        }
        __syncthreads();                                   // sync2
#pragma unroll
        for (int k = 0; k < 8; k++) {
            rA[k] = buf[0][t + THREADS * k];
            rB[k] = buf[1][t + THREADS * k];
        }

        // ======== Layer 2 (real RY) ========
#pragma unroll
        for (int j = 0; j < 3; j++) {                     // q0,q1,q2 -> kb 2,1,0
            const ull* g = sg + CRY + 4 * j;
            ull c2 = g[0], s2 = g[1], ns2 = g[2];
            rgate_body(rA, c2, s2, ns2, 2 - j);
            rgate_body(rB, c2, s2, ns2, 2 - j);
        }
#pragma unroll
        for (int j = 5; j < 10; j++) {                    // q5..q9 -> lb 4..0
            const ull* g = sg + CRY + 4 * j;
            const int lb = 9 - j;
            const bool hi = (lane >> lb) & 1;
            ull c2 = g[0];
            ull q2 = hi ? g[1] : g[2];
            rshfl_body(rA, c2, q2, lb);
            rshfl_body(rB, c2, q2, lb);
        }

        __syncthreads();                                   // sync2w (WAR on buf)

        // ---- Exchange 3: A -> B layout ----
#pragma unroll
        for (int k = 0; k < 8; k++) {
            buf[0][t + THREADS * k] = rA[k];
            buf[1][t + THREADS * k] = rB[k];
        }
        __syncthreads();                                   // sync3
#pragma unroll
        for (int k = 0; k < 8; k++) {
            const int idx = lane | (k << 5) | (w << 8);
            rA[k] = buf[0][idx];
            rB[k] = buf[1][idx];
        }
        {
            const ull* g = sg + CRY + 4 * 4;               // q4 (kb0)
            ull c2 = g[0], s2 = g[1], ns2 = g[2];
            rgate_body(rA, c2, s2, ns2, 0);
            rgate_body(rB, c2, s2, ns2, 0);
        }
        {
            const ull* g = sg + CRY + 4 * 3;               // q3 (kb1)
            ull c2 = g[0], s2 = g[1], ns2 = g[2];
            rgate_body(rA, c2, s2, ns2, 1);
            rgate_body(rB, c2, s2, ns2, 1);
        }

        // ======== <Z_j> reductions into parity slot (read next iteration) ====
        zreduce(rA, lane, w, swred[par][0]);
        zreduce(rB, lane, w, swred[par][1]);

        prevA = rowA;
    }

    // ---- Final pair output (one trailing barrier makes all writes visible) ----
    __syncthreads();
    if (prevA >= 0) {
        const int q = par ^ 1;          // parity slot of the last iteration
        if (t < NW) {
            const float* sw = swred[q][0];
            float e   = sw[t]  + sw[12 + t]  + sw[24 + t]  + sw[36 + t];
            float tot = sw[10] + sw[12 + 10] + sw[24 + 10] + sw[36 + 10];
            out[(size_t)prevA * NW + t] = e / fmaxf(tot, 1e-30f);
        } else if (t >= 32 && t < 32 + NW) {
            const int tt = t - 32;
            const float* sw = swred[q][1];
            float e   = sw[tt] + sw[12 + tt] + sw[24 + tt] + sw[36 + tt];
            float tot = sw[10] + sw[12 + 10] + sw[24 + 10] + sw[36 + 10];
            out[(size_t)(prevA + 1) * NW + tt] = e / fmaxf(tot, 1e-30f);
        }
    }
}

extern "C" void kernel_launch(void* const* d_in, const int* in_sizes, int n_in,
                              void* d_out, int out_size) {
    const float* x   = (const float*)d_in[0];
    const float* rx0 = (const float*)d_in[1];
    const float* ry0 = (const float*)d_in[2];
    const float* ry1 = (const float*)d_in[3];
    float* out = (float*)d_out;

    int nrows = in_sizes[0] / DIM;  // 4096
    int npairs = nrows >> 1;        // 2048

    // ~17 KB smem + <=64 regs -> 8 CTAs/SM -> capacity 1184 >= 1024:
    // single wave, every CTA runs exactly 2 pair-iterations.
    int grid = 1024;
    if (grid > npairs) grid = npairs;
    qsa_main<<<grid, THREADS>>>(x, out, nrows, rx0, ry0, ry1);
}